// round 6
// baseline (speedup 1.0000x reference)
#include <cuda_runtime.h>

#define NQ 16
#define BATCH 512
#define MAXT_PER (2048)
#define MAXT (NQ * MAXT_PER)

struct __align__(16) Term {
    unsigned e;   // eval state: 2 bits/qubit, 0=absent 1=cos(phi) 2=-sin(phi)
    unsigned c;   // coeff state: 2 bits/qubit, 0=absent 1=cos(th) 2=sin(th)
    float s;      // +-1 Aaronson-Gottesman sign
    float pad;
};

struct Offs { int o[NQ + 1]; };

__device__ Term g_terms[MAXT];

// ---------------------------------------------------------------------------
// Single GPU kernel: one CTA per sample, one warp per output i.
//   <Z_i>_b = sum_t s_t * prod_p E[p][e_t nibble p] * prod_p W[p][c_t nibble p]
// ---------------------------------------------------------------------------
__global__ __launch_bounds__(512) void eval_kernel(
    const float* __restrict__ zin,
    const float* __restrict__ params,
    const float* __restrict__ w,
    float* __restrict__ out,
    Offs off)
{
    __shared__ float cp[NQ], yp[NQ], ct[NQ], st[NQ];
    __shared__ float E[8][16], W[8][16];   // pair product tables

    const int b = blockIdx.x;
    const int tid = threadIdx.x;
    const int lane = tid & 31;
    const int i = tid >> 5;

    if (tid < NQ) {
        float phi = zin[b * NQ + tid] + params[tid] + w[tid];
        float sp, cpl;  __sincosf(phi, &sp, &cpl);
        cp[tid] = cpl;  yp[tid] = -sp;          // <Z>, <Y> on RX(phi)|0>
        float th = w[NQ + tid];
        float s2, c2;   __sincosf(th, &s2, &c2);
        ct[tid] = c2;   st[tid] = s2;
    }
    __syncthreads();

    if (tid < 128) {                             // E table: phi factors
        int p = tid >> 4, k = tid & 15;
        int s0 = k & 3, s1 = k >> 2;
        float f0 = (s0 == 0) ? 1.f : ((s0 == 1) ? cp[2 * p]     : yp[2 * p]);
        float f1 = (s1 == 0) ? 1.f : ((s1 == 1) ? cp[2 * p + 1] : yp[2 * p + 1]);
        E[p][k] = f0 * f1;
    } else if (tid < 256) {                      // W table: theta factors
        int r = tid - 128;
        int p = r >> 4, k = r & 15;
        int s0 = k & 3, s1 = k >> 2;
        float f0 = (s0 == 0) ? 1.f : ((s0 == 1) ? ct[2 * p]     : st[2 * p]);
        float f1 = (s1 == 0) ? 1.f : ((s1 == 1) ? ct[2 * p + 1] : st[2 * p + 1]);
        W[p][k] = f0 * f1;
    }
    __syncthreads();

    float acc = 0.f;
    for (int t = off.o[i] + lane; t < off.o[i + 1]; t += 32) {
        Term tm = g_terms[t];
        // two independent product chains for ILP
        float p1 = tm.s, p2 = 1.f;
#pragma unroll
        for (int p = 0; p < 8; p += 2) {
            p1 *= E[p][(tm.e >> (4 * p)) & 15];
            p2 *= E[p + 1][(tm.e >> (4 * (p + 1))) & 15];
            p1 *= W[p][(tm.c >> (4 * p)) & 15];
            p2 *= W[p + 1][(tm.c >> (4 * (p + 1))) & 15];
        }
        acc += p1 * p2;
    }
#pragma unroll
    for (int o = 16; o; o >>= 1)
        acc += __shfl_down_sync(0xffffffffu, acc, o);
    if (lane == 0) out[b * NQ + i] = acc;
}

// ---------------------------------------------------------------------------
// Host: data-independent term-structure generation (pure function of the fixed
// circuit topology). Recomputed identically on every call — deterministic.
// ---------------------------------------------------------------------------
static unsigned h_xevolve(unsigned x) {      // x-evolution through C1-conj
    for (int g = 15; g >= 0; g--) {
        int t = (g + 1) & 15;
        x ^= ((x >> g) & 1u) << t;           // x_t ^= x_c (c = g)
    }
    return x;
}

extern "C" void kernel_launch(void* const* d_in, const int* in_sizes, int n_in,
                              void* d_out, int out_size) {
    const float* z      = (const float*)d_in[0];   // [512,16]
    const float* params = (const float*)d_in[1];   // [16]
    const float* w      = (const float*)d_in[2];   // ent_weights [2,16]
    float* out = (float*)d_out;                    // [512,16] float32

    static Term h_terms[MAXT];
    Offs off;
    int total = 0;

    for (int i = 0; i < NQ; i++) {
        off.o[i] = total;
        const unsigned S = (i == 0) ? 0xFFFEu : ((1u << (i + 1)) - 1u);

        // z-evolution through C1-conjugation (a-independent)
        unsigned zz = S;
        for (int g = 15; g >= 0; g--) {
            int t = (g + 1) & 15;
            zz ^= ((zz >> t) & 1u) << g;     // z_c ^= z_t
        }

        // basis of the Y-choice space, then null-space elimination:
        // for every q with zz_q == 0 require x'_q(a) == 0
        unsigned basis[NQ];
        int d = 0;
        for (int q = 0; q < NQ; q++)
            if ((S >> q) & 1) basis[d++] = 1u << q;

        for (int q = 0; q < NQ; q++) {
            if ((zz >> q) & 1) continue;
            int piv = -1;
            unsigned dot[NQ];
            for (int k = 0; k < d; k++) {
                dot[k] = (h_xevolve(basis[k]) >> q) & 1u;
                if (dot[k] && piv < 0) piv = k;
            }
            if (piv < 0) continue;
            for (int k = 0; k < d; k++)
                if (dot[k] && k != piv) basis[k] ^= basis[piv];
            basis[piv] = basis[d - 1];
            d--;
        }

        long long cnt = 1ll << d;
        if (cnt > MAXT_PER) cnt = MAXT_PER;  // defensive; never hit (d <= 11)

        for (long long j = 0; j < cnt; j++) {
            unsigned a = 0;
            for (int k = 0; k < d; k++)
                if ((j >> k) & 1) a ^= basis[k];

            // full symplectic conjugation with A-G sign tracking
            unsigned x = a, zv = S, sgn = 0;
            for (int g = 15; g >= 0; g--) {
                int c = g, t = (g + 1) & 15;
                unsigned xc = (x >> c) & 1u, zt = (zv >> t) & 1u;
                unsigned xt = (x >> t) & 1u, zc = (zv >> c) & 1u;
                sgn ^= xc & zt & (xt ^ zc ^ 1u);
                x  ^= xc << t;
                zv ^= zt << c;
            }

            unsigned es = 0, cs = 0;
            for (int q = 0; q < NQ; q++) {
                if ((zz >> q) & 1)
                    es |= (((x >> q) & 1u) ? 2u : 1u) << (2 * q);
                if ((S >> q) & 1)
                    cs |= (((a >> q) & 1u) ? 2u : 1u) << (2 * q);
            }
            h_terms[total].e = es;
            h_terms[total].c = cs;
            h_terms[total].s = sgn ? -1.f : 1.f;
            h_terms[total].pad = 0.f;
            total++;
        }
    }
    off.o[NQ] = total;

    // ship the (data-independent) term table; captured as one H2D memcpy node
    cudaMemcpyToSymbolAsync(g_terms, h_terms, (size_t)total * sizeof(Term),
                            0, cudaMemcpyHostToDevice, 0);

    eval_kernel<<<BATCH, 512>>>(z, params, w, out, off);
}

// round 7
// speedup vs baseline: 2.9924x; 2.9924x over previous
#include <cuda_runtime.h>

#define NQ 16
#define BATCH 512
#define MAXT 8192

// ---------------------------------------------------------------------------
// Compile-time Pauli back-propagation term table.
//   <Z_i> = <0| Ra† C1† R2† C2† Z_i C2 R2 C1 Ra |0>
//   C2†ZiC2 = Z_{S_i}; R2 expands each Z_q into cos·Z + sin·Y; C1-conjugation
//   is symplectic (x_t^=x_c, z_c^=z_t, A-G sign); on RX(phi)|0>: <Z>=cos phi,
//   <Y>=-sin phi, <X>=0. Survivors of "no final X" form a GF(2) subspace in
//   the Y-choice mask; we eliminate and enumerate it — all at compile time.
// ---------------------------------------------------------------------------
struct TermTab {
    unsigned e[MAXT];   // 2 bits/qubit: 0=absent 1=cos(phi) 2=-sin(phi)
    unsigned c[MAXT];   // 2 bits/qubit: 0=absent 1=cos(th)  2=sin(th)
    float    s[MAXT];   // +-1 Aaronson-Gottesman sign
    int      off[NQ + 1];
};

constexpr unsigned xevolve(unsigned x) {
    for (int g = 15; g >= 0; g--) { int t = (g + 1) & 15; x ^= ((x >> g) & 1u) << t; }
    return x;
}

constexpr TermTab make_terms() {
    TermTab tt{};
    int total = 0;
    for (int i = 0; i < NQ; i++) {
        tt.off[i] = total;
        const unsigned S = (i == 0) ? 0xFFFEu : ((1u << (i + 1)) - 1u);

        unsigned zz = S;                                   // z-evolution (a-indep)
        for (int g = 15; g >= 0; g--) { int t = (g + 1) & 15; zz ^= ((zz >> t) & 1u) << g; }

        unsigned basis[NQ] = {};
        int d = 0;
        for (int q = 0; q < NQ; q++)
            if ((S >> q) & 1) basis[d++] = 1u << q;

        for (int q = 0; q < NQ; q++) {                     // null-space elimination
            if ((zz >> q) & 1) continue;
            int piv = -1;
            unsigned dot[NQ] = {};
            for (int k = 0; k < d; k++) {
                dot[k] = (xevolve(basis[k]) >> q) & 1u;
                if (dot[k] && piv < 0) piv = k;
            }
            if (piv < 0) continue;
            for (int k = 0; k < d; k++)
                if (dot[k] && k != piv) basis[k] ^= basis[piv];
            basis[piv] = basis[d - 1];
            d--;
        }

        const int cnt = 1 << d;
        for (int j = 0; j < cnt; j++) {
            unsigned a = 0;
            for (int k = 0; k < d; k++)
                if ((j >> k) & 1) a ^= basis[k];

            unsigned x = a, zv = S, sgn = 0;               // symplectic + A-G sign
            for (int g = 15; g >= 0; g--) {
                int c = g, t = (g + 1) & 15;
                unsigned xc = (x >> c) & 1u, zt = (zv >> t) & 1u;
                unsigned xt = (x >> t) & 1u, zc = (zv >> c) & 1u;
                sgn ^= xc & zt & (xt ^ zc ^ 1u);
                x  ^= xc << t;
                zv ^= zt << c;
            }

            unsigned es = 0, cs = 0;
            for (int q = 0; q < NQ; q++) {
                if ((zz >> q) & 1) es |= (((x >> q) & 1u) ? 2u : 1u) << (2 * q);
                if ((S  >> q) & 1) cs |= (((a >> q) & 1u) ? 2u : 1u) << (2 * q);
            }
            tt.e[total] = es;
            tt.c[total] = cs;
            tt.s[total] = sgn ? -1.f : 1.f;
            total++;
        }
    }
    tt.off[NQ] = total;
    return tt;
}

constexpr TermTab TT = make_terms();
constexpr int TOTAL = TT.off[NQ];
static_assert(TOTAL <= MAXT, "term table overflow");
static_assert(TOTAL * 4 <= 32768, "coef smem overflow");

__device__ const TermTab g_tt = TT;   // constexpr-initialized: no runtime copy

// ---------------------------------------------------------------------------
// Single kernel: one CTA per sample, one warp per output i.
// Per CTA: build phi pair-table E (sample-dep) and per-term coefficients
// coef[t] = sign * prod(theta factors) (sample-indep, rebuilt per CTA — cheap),
// then   <Z_i>_b = sum_t coef[t] * prod_p E[p][nibble_p(e_t)].
// ---------------------------------------------------------------------------
__global__ __launch_bounds__(512) void eval_kernel(
    const float* __restrict__ zin,
    const float* __restrict__ params,
    const float* __restrict__ w,
    float* __restrict__ out)
{
    __shared__ float cp[NQ], yp[NQ], ct[NQ], st[NQ];
    __shared__ float E[8][16];
    __shared__ float coef[TOTAL];

    const int b = blockIdx.x;
    const int tid = threadIdx.x;
    const int lane = tid & 31;
    const int i = tid >> 5;

    if (tid < NQ) {
        float phi = zin[b * NQ + tid] + params[tid] + w[tid];
        float sp, cl;  __sincosf(phi, &sp, &cl);
        cp[tid] = cl;  yp[tid] = -sp;               // <Z>, <Y> on RX(phi)|0>
        float th = w[NQ + tid];
        float s2, c2;  __sincosf(th, &s2, &c2);
        ct[tid] = c2;  st[tid] = s2;
    }
    __syncthreads();

    if (tid < 128) {                                 // E: phi pair-product table
        int p = tid >> 4, k = tid & 15;
        int s0 = k & 3, s1 = k >> 2;
        float f0 = (s0 == 0) ? 1.f : ((s0 == 1) ? cp[2 * p]     : yp[2 * p]);
        float f1 = (s1 == 0) ? 1.f : ((s1 == 1) ? cp[2 * p + 1] : yp[2 * p + 1]);
        E[p][k] = f0 * f1;
    }
    for (int t = tid; t < TOTAL; t += 512) {         // per-term theta coefficient
        unsigned cs = g_tt.c[t];
        float p = g_tt.s[t];
#pragma unroll
        for (int q = 0; q < NQ; q++) {
            int sel = (cs >> (2 * q)) & 3;
            if (sel) p *= (sel == 1) ? ct[q] : st[q];
        }
        coef[t] = p;
    }
    __syncthreads();

    const int lo = g_tt.off[i], hi = g_tt.off[i + 1];
    float acc = 0.f;
    for (int t = lo + lane; t < hi; t += 32) {
        unsigned e = g_tt.e[t];
        float p1 = coef[t], p2 = 1.f;                // two chains for ILP
        p1 *= E[0][ e        & 15];
        p2 *= E[1][(e >>  4) & 15];
        p1 *= E[2][(e >>  8) & 15];
        p2 *= E[3][(e >> 12) & 15];
        p1 *= E[4][(e >> 16) & 15];
        p2 *= E[5][(e >> 20) & 15];
        p1 *= E[6][(e >> 24) & 15];
        p2 *= E[7][(e >> 28) & 15];
        acc = fmaf(p1, p2, acc);
    }
#pragma unroll
    for (int o = 16; o; o >>= 1)
        acc += __shfl_down_sync(0xffffffffu, acc, o);
    if (lane == 0) out[b * NQ + i] = acc;
}

extern "C" void kernel_launch(void* const* d_in, const int* in_sizes, int n_in,
                              void* d_out, int out_size) {
    const float* z      = (const float*)d_in[0];   // [512,16]
    const float* params = (const float*)d_in[1];   // [16]
    const float* w      = (const float*)d_in[2];   // ent_weights [2,16]
    float* out = (float*)d_out;                    // [512,16] float32

    eval_kernel<<<BATCH, 512>>>(z, params, w, out);
}

// round 8
// speedup vs baseline: 4.2107x; 1.4071x over previous
#include <cuda_runtime.h>

#define NQ 16
#define BATCH 512
#define MAXT 8192
#define MAXG 384
#define MAXP (MAXT + MAXG * 31)
#define NWARP 8

// ---------------------------------------------------------------------------
// Compile-time Pauli back-propagation term table (identical math to R6, which
// passed at rel_err 9e-6), then padded into 32-term groups with a round-robin
// warp schedule — all constexpr, zero runtime build cost.
// ---------------------------------------------------------------------------
struct TermTab {
    unsigned e[MAXT];   // 2 bits/qubit: 0=absent 1=cos(phi) 2=-sin(phi)
    unsigned c[MAXT];   // 2 bits/qubit: 0=absent 1=cos(th)  2=sin(th)
    float    s[MAXT];   // +-1 Aaronson-Gottesman sign
    int      off[NQ + 1];
};

constexpr unsigned xevolve(unsigned x) {
    for (int g = 15; g >= 0; g--) { int t = (g + 1) & 15; x ^= ((x >> g) & 1u) << t; }
    return x;
}

constexpr TermTab make_terms() {
    TermTab tt{};
    int total = 0;
    for (int i = 0; i < NQ; i++) {
        tt.off[i] = total;
        const unsigned S = (i == 0) ? 0xFFFEu : ((1u << (i + 1)) - 1u);

        unsigned zz = S;                                   // z-evolution (a-indep)
        for (int g = 15; g >= 0; g--) { int t = (g + 1) & 15; zz ^= ((zz >> t) & 1u) << g; }

        unsigned basis[NQ] = {};
        int d = 0;
        for (int q = 0; q < NQ; q++)
            if ((S >> q) & 1) basis[d++] = 1u << q;

        for (int q = 0; q < NQ; q++) {                     // null-space elimination
            if ((zz >> q) & 1) continue;
            int piv = -1;
            unsigned dot[NQ] = {};
            for (int k = 0; k < d; k++) {
                dot[k] = (xevolve(basis[k]) >> q) & 1u;
                if (dot[k] && piv < 0) piv = k;
            }
            if (piv < 0) continue;
            for (int k = 0; k < d; k++)
                if (dot[k] && k != piv) basis[k] ^= basis[piv];
            basis[piv] = basis[d - 1];
            d--;
        }

        const int cnt = 1 << d;
        for (int j = 0; j < cnt; j++) {
            unsigned a = 0;
            for (int k = 0; k < d; k++)
                if ((j >> k) & 1) a ^= basis[k];

            unsigned x = a, zv = S, sgn = 0;               // symplectic + A-G sign
            for (int g = 15; g >= 0; g--) {
                int c = g, t = (g + 1) & 15;
                unsigned xc = (x >> c) & 1u, zt = (zv >> t) & 1u;
                unsigned xt = (x >> t) & 1u, zc = (zv >> c) & 1u;
                sgn ^= xc & zt & (xt ^ zc ^ 1u);
                x  ^= xc << t;
                zv ^= zt << c;
            }

            unsigned es = 0, cs = 0;
            for (int q = 0; q < NQ; q++) {
                if ((zz >> q) & 1) es |= (((x >> q) & 1u) ? 2u : 1u) << (2 * q);
                if ((S  >> q) & 1) cs |= (((a >> q) & 1u) ? 2u : 1u) << (2 * q);
            }
            tt.e[total] = es;
            tt.c[total] = cs;
            tt.s[total] = sgn ? -1.f : 1.f;
            total++;
        }
    }
    tt.off[NQ] = total;
    return tt;
}

struct __align__(16) PTerm { unsigned e, c; float s, pad; };

struct Padded {
    PTerm t[MAXP];
    int   goid[MAXG];   // output id of each 32-term group
    int   G;            // number of groups
};

constexpr Padded make_padded() {
    const TermTab tt = make_terms();
    Padded P{};
    int g = 0, pos = 0;
    for (int i = 0; i < NQ; i++) {
        for (int base = tt.off[i]; base < tt.off[i + 1]; base += 32) {
            P.goid[g] = i;
            for (int k = 0; k < 32; k++) {
                int idx = base + k;
                if (idx < tt.off[i + 1]) {
                    P.t[pos].e = tt.e[idx];
                    P.t[pos].c = tt.c[idx];
                    P.t[pos].s = tt.s[idx];
                } else {
                    P.t[pos].e = 0; P.t[pos].c = 0; P.t[pos].s = 0.f;  // pad: contributes 0
                }
                P.t[pos].pad = 0.f;
                pos++;
            }
            g++;
        }
    }
    P.G = g;
    return P;
}

constexpr Padded PP = make_padded();
constexpr int G = PP.G;
static_assert(make_terms().off[NQ] <= MAXT, "term overflow");
static_assert(G <= MAXG, "group overflow");

__device__ const Padded g_pp = PP;   // constexpr-initialized device global

// ---------------------------------------------------------------------------
// One CTA (256 thr, 8 warps) per sample. Warps round-robin the term groups
// (uniform 32-term units -> balanced). Per term: one LDG.128 + 16 LDS pair-
// table lookups + ~17 FMUL. Group result: 5-shfl reduce -> part[warp][oid].
// ---------------------------------------------------------------------------
__global__ __launch_bounds__(256) void eval_kernel(
    const float* __restrict__ zin,
    const float* __restrict__ params,
    const float* __restrict__ w,
    float* __restrict__ out)
{
    __shared__ float cp[NQ], yp[NQ], ct[NQ], st[NQ];
    __shared__ float E[8][16], W[8][16];
    __shared__ float part[NWARP][16];

    const int b = blockIdx.x;
    const int tid = threadIdx.x;
    const int lane = tid & 31;
    const int wp = tid >> 5;

    if (tid < NQ) {
        float phi = zin[b * NQ + tid] + params[tid] + w[tid];
        float sp, cl;  __sincosf(phi, &sp, &cl);
        cp[tid] = cl;  yp[tid] = -sp;               // <Z>, <Y> on RX(phi)|0>
        float th = w[NQ + tid];
        float s2, c2;  __sincosf(th, &s2, &c2);
        ct[tid] = c2;  st[tid] = s2;
    }
    __syncthreads();

    if (tid < 128) {                                 // E: phi pair-products
        int p = tid >> 4, k = tid & 15;
        int s0 = k & 3, s1 = k >> 2;
        float f0 = (s0 == 0) ? 1.f : ((s0 == 1) ? cp[2 * p]     : yp[2 * p]);
        float f1 = (s1 == 0) ? 1.f : ((s1 == 1) ? cp[2 * p + 1] : yp[2 * p + 1]);
        E[p][k] = f0 * f1;
        part[tid >> 4][tid & 15] = 0.f;              // zero the partials
    } else {                                         // W: theta pair-products
        int r = tid - 128;
        int p = r >> 4, k = r & 15;
        int s0 = k & 3, s1 = k >> 2;
        float f0 = (s0 == 0) ? 1.f : ((s0 == 1) ? ct[2 * p]     : st[2 * p]);
        float f1 = (s1 == 0) ? 1.f : ((s1 == 1) ? ct[2 * p + 1] : st[2 * p + 1]);
        W[p][k] = f0 * f1;
    }
    __syncthreads();

#pragma unroll
    for (int g = wp; g < G; g += NWARP) {
        const PTerm tm = g_pp.t[g * 32 + lane];
        const unsigned e = tm.e, c = tm.c;
        float p1 = tm.s, p2 = 1.f;                   // two chains for ILP
        p1 *= E[0][ e        & 15];  p2 *= E[1][(e >>  4) & 15];
        p1 *= E[2][(e >>  8) & 15];  p2 *= E[3][(e >> 12) & 15];
        p1 *= E[4][(e >> 16) & 15];  p2 *= E[5][(e >> 20) & 15];
        p1 *= E[6][(e >> 24) & 15];  p2 *= E[7][(e >> 28) & 15];
        p1 *= W[0][ c        & 15];  p2 *= W[1][(c >>  4) & 15];
        p1 *= W[2][(c >>  8) & 15];  p2 *= W[3][(c >> 12) & 15];
        p1 *= W[4][(c >> 16) & 15];  p2 *= W[5][(c >> 20) & 15];
        p1 *= W[6][(c >> 24) & 15];  p2 *= W[7][(c >> 28) & 15];
        float v = p1 * p2;
#pragma unroll
        for (int o = 16; o; o >>= 1)
            v += __shfl_down_sync(0xffffffffu, v, o);
        if (lane == 0) part[wp][g_pp.goid[g]] += v;  // warp-private row
    }
    __syncthreads();

    if (tid < NQ) {
        float s = 0.f;
#pragma unroll
        for (int k = 0; k < NWARP; k++) s += part[k][tid];
        out[b * NQ + tid] = s;
    }
}

extern "C" void kernel_launch(void* const* d_in, const int* in_sizes, int n_in,
                              void* d_out, int out_size) {
    const float* z      = (const float*)d_in[0];   // [512,16]
    const float* params = (const float*)d_in[1];   // [16]
    const float* w      = (const float*)d_in[2];   // ent_weights [2,16]
    float* out = (float*)d_out;                    // [512,16] float32

    eval_kernel<<<BATCH, 256>>>(z, params, w, out);
}

// round 9
// speedup vs baseline: 4.2258x; 1.0036x over previous
#include <cuda_runtime.h>

#define NQ 16
#define BATCH 512
#define MAXT 8192
#define MAXG 384
#define MAXP (MAXT + MAXG * 31)
#define NWARP 8
#define S 4                       // samples per CTA
#define GRID (BATCH / S)

// ---------------------------------------------------------------------------
// Compile-time Pauli back-propagation term table (identical math to R6/R7,
// both passed at rel_err ~9e-6), padded into 32-term groups — all constexpr.
// ---------------------------------------------------------------------------
struct TermTab {
    unsigned e[MAXT];   // 2 bits/qubit: 0=absent 1=cos(phi) 2=-sin(phi)
    unsigned c[MAXT];   // 2 bits/qubit: 0=absent 1=cos(th)  2=sin(th)
    float    s[MAXT];   // +-1 Aaronson-Gottesman sign
    int      off[NQ + 1];
};

constexpr unsigned xevolve(unsigned x) {
    for (int g = 15; g >= 0; g--) { int t = (g + 1) & 15; x ^= ((x >> g) & 1u) << t; }
    return x;
}

constexpr TermTab make_terms() {
    TermTab tt{};
    int total = 0;
    for (int i = 0; i < NQ; i++) {
        tt.off[i] = total;
        const unsigned Sm = (i == 0) ? 0xFFFEu : ((1u << (i + 1)) - 1u);

        unsigned zz = Sm;                                  // z-evolution (a-indep)
        for (int g = 15; g >= 0; g--) { int t = (g + 1) & 15; zz ^= ((zz >> t) & 1u) << g; }

        unsigned basis[NQ] = {};
        int d = 0;
        for (int q = 0; q < NQ; q++)
            if ((Sm >> q) & 1) basis[d++] = 1u << q;

        for (int q = 0; q < NQ; q++) {                     // null-space elimination
            if ((zz >> q) & 1) continue;
            int piv = -1;
            unsigned dot[NQ] = {};
            for (int k = 0; k < d; k++) {
                dot[k] = (xevolve(basis[k]) >> q) & 1u;
                if (dot[k] && piv < 0) piv = k;
            }
            if (piv < 0) continue;
            for (int k = 0; k < d; k++)
                if (dot[k] && k != piv) basis[k] ^= basis[piv];
            basis[piv] = basis[d - 1];
            d--;
        }

        const int cnt = 1 << d;
        for (int j = 0; j < cnt; j++) {
            unsigned a = 0;
            for (int k = 0; k < d; k++)
                if ((j >> k) & 1) a ^= basis[k];

            unsigned x = a, zv = Sm, sgn = 0;              // symplectic + A-G sign
            for (int g = 15; g >= 0; g--) {
                int c = g, t = (g + 1) & 15;
                unsigned xc = (x >> c) & 1u, zt = (zv >> t) & 1u;
                unsigned xt = (x >> t) & 1u, zc = (zv >> c) & 1u;
                sgn ^= xc & zt & (xt ^ zc ^ 1u);
                x  ^= xc << t;
                zv ^= zt << c;
            }

            unsigned es = 0, cs = 0;
            for (int q = 0; q < NQ; q++) {
                if ((zz >> q) & 1) es |= (((x >> q) & 1u) ? 2u : 1u) << (2 * q);
                if ((Sm >> q) & 1) cs |= (((a >> q) & 1u) ? 2u : 1u) << (2 * q);
            }
            tt.e[total] = es;
            tt.c[total] = cs;
            tt.s[total] = sgn ? -1.f : 1.f;
            total++;
        }
    }
    tt.off[NQ] = total;
    return tt;
}

struct __align__(16) PTerm { unsigned e, c; float s, pad; };

struct Padded {
    PTerm t[MAXP];
    int   goid[MAXG];
    int   G;
};

constexpr Padded make_padded() {
    const TermTab tt = make_terms();
    Padded P{};
    int g = 0, pos = 0;
    for (int i = 0; i < NQ; i++) {
        for (int base = tt.off[i]; base < tt.off[i + 1]; base += 32) {
            P.goid[g] = i;
            for (int k = 0; k < 32; k++) {
                int idx = base + k;
                if (idx < tt.off[i + 1]) {
                    P.t[pos].e = tt.e[idx];
                    P.t[pos].c = tt.c[idx];
                    P.t[pos].s = tt.s[idx];
                } else {
                    P.t[pos].e = 0; P.t[pos].c = 0; P.t[pos].s = 0.f;  // pad -> 0
                }
                P.t[pos].pad = 0.f;
                pos++;
            }
            g++;
        }
    }
    P.G = g;
    return P;
}

constexpr Padded PP = make_padded();
constexpr int G = PP.G;
static_assert(make_terms().off[NQ] <= MAXT, "term overflow");
static_assert(G <= MAXG, "group overflow");

__device__ const Padded g_pp = PP;

// ---------------------------------------------------------------------------
// One CTA (256 thr) per 4 samples -> grid 128, one wave. Warps round-robin
// the 32-term groups. Per term: w-product (sample-indep) computed once,
// then 4 sample E-products; 4 pipelined shfl reduces -> part[warp][smp][oid].
// ---------------------------------------------------------------------------
__global__ __launch_bounds__(256) void eval_kernel(
    const float* __restrict__ zin,
    const float* __restrict__ params,
    const float* __restrict__ w,
    float* __restrict__ out)
{
    __shared__ float cps[S][NQ], yps[S][NQ], ct[NQ], st[NQ];
    __shared__ float E[S][8][16], W[8][16];
    __shared__ float part[NWARP][S][16];

    const int b0 = blockIdx.x * S;
    const int tid = threadIdx.x;
    const int lane = tid & 31;
    const int wp = tid >> 5;

    if (tid < S * NQ) {                              // 64 threads: phi angles
        int smp = tid >> 4, q = tid & 15;
        float phi = zin[(b0 + smp) * NQ + q] + params[q] + w[q];
        float sp, cl;  __sincosf(phi, &sp, &cl);
        cps[smp][q] = cl;  yps[smp][q] = -sp;        // <Z>, <Y> on RX(phi)|0>
    } else if (tid < S * NQ + NQ) {                  // 16 threads: theta angles
        int q = tid - S * NQ;
        float s2, c2;  __sincosf(w[NQ + q], &s2, &c2);
        ct[q] = c2;  st[q] = s2;
    }
    __syncthreads();

    for (int k = tid; k < S * 128; k += 256) {       // E: per-sample pair tables
        int smp = k >> 7, r = k & 127;
        int p = r >> 4, idx = r & 15;
        int s0 = idx & 3, s1 = idx >> 2;
        float f0 = (s0 == 0) ? 1.f : ((s0 == 1) ? cps[smp][2 * p]     : yps[smp][2 * p]);
        float f1 = (s1 == 0) ? 1.f : ((s1 == 1) ? cps[smp][2 * p + 1] : yps[smp][2 * p + 1]);
        E[smp][p][idx] = f0 * f1;
    }
    if (tid < 128) {                                 // W: theta pair table
        int p = tid >> 4, idx = tid & 15;
        int s0 = idx & 3, s1 = idx >> 2;
        float f0 = (s0 == 0) ? 1.f : ((s0 == 1) ? ct[2 * p]     : st[2 * p]);
        float f1 = (s1 == 0) ? 1.f : ((s1 == 1) ? ct[2 * p + 1] : st[2 * p + 1]);
        W[p][idx] = f0 * f1;
    }
    for (int k = tid; k < NWARP * S * 16; k += 256)  // zero partials
        ((float*)part)[k] = 0.f;
    __syncthreads();

#pragma unroll
    for (int g = wp; g < G; g += NWARP) {
        const PTerm tm = g_pp.t[g * 32 + lane];
        const unsigned e = tm.e, c = tm.c;

        float w1 = tm.s, w2 = 1.f;                   // sample-independent product
        w1 *= W[0][ c        & 15];  w2 *= W[1][(c >>  4) & 15];
        w1 *= W[2][(c >>  8) & 15];  w2 *= W[3][(c >> 12) & 15];
        w1 *= W[4][(c >> 16) & 15];  w2 *= W[5][(c >> 20) & 15];
        w1 *= W[6][(c >> 24) & 15];  w2 *= W[7][(c >> 28) & 15];
        const float wprod = w1 * w2;

        float v[S];
#pragma unroll
        for (int smp = 0; smp < S; smp++) {
            float p1 = wprod, p2 = 1.f;
            p1 *= E[smp][0][ e        & 15];  p2 *= E[smp][1][(e >>  4) & 15];
            p1 *= E[smp][2][(e >>  8) & 15];  p2 *= E[smp][3][(e >> 12) & 15];
            p1 *= E[smp][4][(e >> 16) & 15];  p2 *= E[smp][5][(e >> 20) & 15];
            p1 *= E[smp][6][(e >> 24) & 15];  p2 *= E[smp][7][(e >> 28) & 15];
            v[smp] = p1 * p2;
        }
#pragma unroll
        for (int o = 16; o; o >>= 1) {               // 4 independent, pipelined
#pragma unroll
            for (int smp = 0; smp < S; smp++)
                v[smp] += __shfl_down_sync(0xffffffffu, v[smp], o);
        }
        if (lane == 0) {
            const int oid = g_pp.goid[g];
#pragma unroll
            for (int smp = 0; smp < S; smp++)
                part[wp][smp][oid] += v[smp];
        }
    }
    __syncthreads();

    if (tid < S * NQ) {
        int smp = tid >> 4, q = tid & 15;
        float sum = 0.f;
#pragma unroll
        for (int k = 0; k < NWARP; k++) sum += part[k][smp][q];
        out[(b0 + smp) * NQ + q] = sum;
    }
}

extern "C" void kernel_launch(void* const* d_in, const int* in_sizes, int n_in,
                              void* d_out, int out_size) {
    const float* z      = (const float*)d_in[0];   // [512,16]
    const float* params = (const float*)d_in[1];   // [16]
    const float* w      = (const float*)d_in[2];   // ent_weights [2,16]
    float* out = (float*)d_out;                    // [512,16] float32

    eval_kernel<<<GRID, 256>>>(z, params, w, out);
}

// round 10
// speedup vs baseline: 5.0170x; 1.1872x over previous
#include <cuda_runtime.h>

#define NQ 16
#define BATCH 512
#define MAXT 8192
#define MAXG 384
#define MAXP (MAXT + MAXG * 31)
#define NWARP 16
#define S 4                       // samples per CTA
#define GRID (BATCH / S)

// ---------------------------------------------------------------------------
// Compile-time Pauli back-propagation term table (identical math to R6-R8,
// all passed at rel_err ~9e-6), padded into 32-term groups — all constexpr.
// ---------------------------------------------------------------------------
struct TermTab {
    unsigned e[MAXT];   // 2 bits/qubit: 0=absent 1=cos(phi) 2=-sin(phi)
    unsigned c[MAXT];   // 2 bits/qubit: 0=absent 1=cos(th)  2=sin(th)
    float    s[MAXT];   // +-1 Aaronson-Gottesman sign
    int      off[NQ + 1];
};

constexpr unsigned xevolve(unsigned x) {
    for (int g = 15; g >= 0; g--) { int t = (g + 1) & 15; x ^= ((x >> g) & 1u) << t; }
    return x;
}

constexpr TermTab make_terms() {
    TermTab tt{};
    int total = 0;
    for (int i = 0; i < NQ; i++) {
        tt.off[i] = total;
        const unsigned Sm = (i == 0) ? 0xFFFEu : ((1u << (i + 1)) - 1u);

        unsigned zz = Sm;                                  // z-evolution (a-indep)
        for (int g = 15; g >= 0; g--) { int t = (g + 1) & 15; zz ^= ((zz >> t) & 1u) << g; }

        unsigned basis[NQ] = {};
        int d = 0;
        for (int q = 0; q < NQ; q++)
            if ((Sm >> q) & 1) basis[d++] = 1u << q;

        for (int q = 0; q < NQ; q++) {                     // null-space elimination
            if ((zz >> q) & 1) continue;
            int piv = -1;
            unsigned dot[NQ] = {};
            for (int k = 0; k < d; k++) {
                dot[k] = (xevolve(basis[k]) >> q) & 1u;
                if (dot[k] && piv < 0) piv = k;
            }
            if (piv < 0) continue;
            for (int k = 0; k < d; k++)
                if (dot[k] && k != piv) basis[k] ^= basis[piv];
            basis[piv] = basis[d - 1];
            d--;
        }

        const int cnt = 1 << d;
        for (int j = 0; j < cnt; j++) {
            unsigned a = 0;
            for (int k = 0; k < d; k++)
                if ((j >> k) & 1) a ^= basis[k];

            unsigned x = a, zv = Sm, sgn = 0;              // symplectic + A-G sign
            for (int g = 15; g >= 0; g--) {
                int c = g, t = (g + 1) & 15;
                unsigned xc = (x >> c) & 1u, zt = (zv >> t) & 1u;
                unsigned xt = (x >> t) & 1u, zc = (zv >> c) & 1u;
                sgn ^= xc & zt & (xt ^ zc ^ 1u);
                x  ^= xc << t;
                zv ^= zt << c;
            }

            unsigned es = 0, cs = 0;
            for (int q = 0; q < NQ; q++) {
                if ((zz >> q) & 1) es |= (((x >> q) & 1u) ? 2u : 1u) << (2 * q);
                if ((Sm >> q) & 1) cs |= (((a >> q) & 1u) ? 2u : 1u) << (2 * q);
            }
            tt.e[total] = es;
            tt.c[total] = cs;
            tt.s[total] = sgn ? -1.f : 1.f;
            total++;
        }
    }
    tt.off[NQ] = total;
    return tt;
}

struct __align__(16) PTerm { unsigned e, c; float s; int oid; };

struct Padded {
    PTerm t[MAXP];      // oid replicated into every padded term (pad: s=0)
    int   G;
};

constexpr Padded make_padded() {
    const TermTab tt = make_terms();
    Padded P{};
    int g = 0, pos = 0;
    for (int i = 0; i < NQ; i++) {
        for (int base = tt.off[i]; base < tt.off[i + 1]; base += 32) {
            for (int k = 0; k < 32; k++) {
                int idx = base + k;
                if (idx < tt.off[i + 1]) {
                    P.t[pos].e = tt.e[idx];
                    P.t[pos].c = tt.c[idx];
                    P.t[pos].s = tt.s[idx];
                } else {
                    P.t[pos].e = 0; P.t[pos].c = 0; P.t[pos].s = 0.f;  // pad -> 0
                }
                P.t[pos].oid = i;
                pos++;
            }
            g++;
        }
    }
    P.G = g;
    return P;
}

constexpr Padded PP = make_padded();
constexpr int G = PP.G;
constexpr int MAXIT = (G + NWARP - 1) / NWARP;
static_assert(make_terms().off[NQ] <= MAXT, "term overflow");
static_assert(G <= MAXG, "group overflow");

__device__ const Padded g_pp = PP;

// ---------------------------------------------------------------------------
// One CTA (512 thr, 16 warps) per 4 samples -> grid 128, one wave.
// Entry: every thread PRELOADS its <=MAXIT PTerms (overlaps cold mem latency
// with the prologue), then builds its one E-table entry directly from gmem
// (redundant per-thread sincos beats a sync + SMEM round trip). ONE sync,
// then ~MAXIT group iterations: wprod once, 4 sample products, 4 pipelined
// shfl reduces -> part[warp][smp][oid].
// ---------------------------------------------------------------------------
__global__ __launch_bounds__(512) void eval_kernel(
    const float* __restrict__ zin,
    const float* __restrict__ params,
    const float* __restrict__ w,
    float* __restrict__ out)
{
    __shared__ float E[S][8][16], W[8][16];
    __shared__ float part[NWARP][S][16];

    const int b0 = blockIdx.x * S;
    const int tid = threadIdx.x;
    const int lane = tid & 31;
    const int wp = tid >> 5;

    // ---- preload term data first: cold LDGs overlap everything below ----
    PTerm tm[MAXIT];
#pragma unroll
    for (int it = 0; it < MAXIT; it++) {
        int g = wp + it * NWARP;
        if (g < G) tm[it] = g_pp.t[g * 32 + lane];
        else       { tm[it].e = 0; tm[it].c = 0; tm[it].s = 0.f; tm[it].oid = 0; }
    }

    // ---- fused prologue: 512 threads == 512 E entries ----
    {
        const int smp = tid >> 7, r = tid & 127;
        const int p = r >> 4, k = r & 15;
        const int s0 = k & 3, s1 = k >> 2;
        float ph0 = zin[(b0 + smp) * NQ + 2 * p]     + params[2 * p]     + w[2 * p];
        float ph1 = zin[(b0 + smp) * NQ + 2 * p + 1] + params[2 * p + 1] + w[2 * p + 1];
        float sn0, cs0, sn1, cs1;
        __sincosf(ph0, &sn0, &cs0);
        __sincosf(ph1, &sn1, &cs1);
        float f0 = (s0 == 0) ? 1.f : ((s0 == 1) ? cs0 : -sn0);   // <Z>=cos, <Y>=-sin
        float f1 = (s1 == 0) ? 1.f : ((s1 == 1) ? cs1 : -sn1);
        E[smp][p][k] = f0 * f1;
    }
    if (tid < 128) {                                 // W pair table (theta)
        const int p = tid >> 4, k = tid & 15;
        const int s0 = k & 3, s1 = k >> 2;
        float sn0, cs0, sn1, cs1;
        __sincosf(w[NQ + 2 * p],     &sn0, &cs0);
        __sincosf(w[NQ + 2 * p + 1], &sn1, &cs1);
        float f0 = (s0 == 0) ? 1.f : ((s0 == 1) ? cs0 : sn0);
        float f1 = (s1 == 0) ? 1.f : ((s1 == 1) ? cs1 : sn1);
        W[p][k] = f0 * f1;
    }
#pragma unroll
    for (int k = tid; k < NWARP * S * 16; k += 512)  // zero partials
        ((float*)part)[k] = 0.f;
    __syncthreads();

    // ---- term loop: terms already in registers ----
#pragma unroll
    for (int it = 0; it < MAXIT; it++) {
        const int g = wp + it * NWARP;
        if (g >= G) break;
        const unsigned e = tm[it].e, c = tm[it].c;

        float w1 = tm[it].s, w2 = 1.f;               // sample-independent product
        w1 *= W[0][ c        & 15];  w2 *= W[1][(c >>  4) & 15];
        w1 *= W[2][(c >>  8) & 15];  w2 *= W[3][(c >> 12) & 15];
        w1 *= W[4][(c >> 16) & 15];  w2 *= W[5][(c >> 20) & 15];
        w1 *= W[6][(c >> 24) & 15];  w2 *= W[7][(c >> 28) & 15];
        const float wprod = w1 * w2;

        float v[S];
#pragma unroll
        for (int smp = 0; smp < S; smp++) {
            float p1 = wprod, p2 = 1.f;
            p1 *= E[smp][0][ e        & 15];  p2 *= E[smp][1][(e >>  4) & 15];
            p1 *= E[smp][2][(e >>  8) & 15];  p2 *= E[smp][3][(e >> 12) & 15];
            p1 *= E[smp][4][(e >> 16) & 15];  p2 *= E[smp][5][(e >> 20) & 15];
            p1 *= E[smp][6][(e >> 24) & 15];  p2 *= E[smp][7][(e >> 28) & 15];
            v[smp] = p1 * p2;
        }
#pragma unroll
        for (int o = 16; o; o >>= 1) {               // 4 independent, pipelined
#pragma unroll
            for (int smp = 0; smp < S; smp++)
                v[smp] += __shfl_down_sync(0xffffffffu, v[smp], o);
        }
        if (lane == 0) {
            const int oid = tm[it].oid;
#pragma unroll
            for (int smp = 0; smp < S; smp++)
                part[wp][smp][oid] += v[smp];
        }
    }
    __syncthreads();

    if (tid < S * NQ) {
        const int smp = tid >> 4, q = tid & 15;
        float sum = 0.f;
#pragma unroll
        for (int k = 0; k < NWARP; k++) sum += part[k][smp][q];
        out[(b0 + smp) * NQ + q] = sum;
    }
}

extern "C" void kernel_launch(void* const* d_in, const int* in_sizes, int n_in,
                              void* d_out, int out_size) {
    const float* z      = (const float*)d_in[0];   // [512,16]
    const float* params = (const float*)d_in[1];   // [16]
    const float* w      = (const float*)d_in[2];   // ent_weights [2,16]
    float* out = (float*)d_out;                    // [512,16] float32

    eval_kernel<<<GRID, 512>>>(z, params, w, out);
}